// round 9
// baseline (speedup 1.0000x reference)
#include <cuda_runtime.h>
#include <cuda_fp16.h>
#include <cstdint>

// ---------------------------------------------------------------------------
// LiquidNeuralNetwork via mma.sync HMMA, M=32 per warp (2x m16 blocks).
// 2-product GEMMs: Ah*(Wh+Wl), fp32 accum; each W fragment load feeds 4 MMAs
// (2 row-blocks x hi/lo) -> W crossbar traffic per row halved vs R8.
// CTA = 128 rows / 4 warps, 2 CTAs/SM. y fp32 + accY fp16 in registers;
// 5 fp16 DOPRI5 stage accumulators in SMEM (HFMA2 RMW); tanh.approx.
// ---------------------------------------------------------------------------

#define LNN_DIN    14
#define LNN_DOUT   3
#define LNN_M      128
#define LNN_NT     128
#define LNN_NSTEPS 32

// SMEM byte offsets
#define OFF_W1   0            // [4kt][8j][32lane] uint4 {h01,h89,l01,l89} = 16KB
#define OFF_W2   16384
#define OFF_ACC  32768        // 5 arrays x 16KB: [m][w][blk][p][lane] uint4
#define OFF_B1   114688       // 64 f32
#define OFF_B2   114944
#define SMEM_SZ  115200

// DOPRI5: CT2[s][m] = coefficient of k_{s+1} in the input sum of stage m+2
static __device__ constexpr float CT2[5][5] = {
    {(float)(1.0/5.0), (float)(3.0/40.0), (float)(44.0/45.0),
     (float)(19372.0/6561.0), (float)(9017.0/3168.0)},
    {0.f, (float)(9.0/40.0), (float)(-56.0/15.0),
     (float)(-25360.0/2187.0), (float)(-355.0/33.0)},
    {0.f, 0.f, (float)(32.0/9.0), (float)(64448.0/6561.0), (float)(46732.0/5247.0)},
    {0.f, 0.f, 0.f, (float)(-212.0/729.0), (float)(49.0/176.0)},
    {0.f, 0.f, 0.f, 0.f, (float)(-5103.0/18656.0)},
};
static __device__ constexpr float BC[6] = {
    (float)(35.0/384.0), 0.f, (float)(500.0/1113.0), (float)(125.0/192.0),
    (float)(-2187.0/6784.0), (float)(11.0/84.0)};

__device__ __forceinline__ void mma8(float* d, uint32_t a0, uint32_t a1,
                                     uint32_t a2, uint32_t a3,
                                     uint32_t b0, uint32_t b1) {
    asm("mma.sync.aligned.m16n8k16.row.col.f32.f16.f16.f32 "
        "{%0,%1,%2,%3}, {%4,%5,%6,%7}, {%8,%9}, {%0,%1,%2,%3};"
        : "+f"(d[0]), "+f"(d[1]), "+f"(d[2]), "+f"(d[3])
        : "r"(a0), "r"(a1), "r"(a2), "r"(a3), "r"(b0), "r"(b1));
}

__device__ __forceinline__ uint32_t packh2(float a, float b) {
    __half2 h = __floats2half2_rn(a, b);
    return *reinterpret_cast<uint32_t*>(&h);
}
__device__ __forceinline__ uint32_t hfma2u(uint32_t a, uint32_t b, uint32_t c) {
    __half2 r = __hfma2(*reinterpret_cast<__half2*>(&a),
                        *reinterpret_cast<__half2*>(&b),
                        *reinterpret_cast<__half2*>(&c));
    return *reinterpret_cast<uint32_t*>(&r);
}
__device__ __forceinline__ uint32_t hmul2u(uint32_t a, uint32_t b) {
    __half2 r = __hmul2(*reinterpret_cast<__half2*>(&a),
                        *reinterpret_cast<__half2*>(&b));
    return *reinterpret_cast<uint32_t*>(&r);
}
__device__ __forceinline__ void pack_hilo(float a, float b,
                                          uint32_t& h, uint32_t& l) {
    __half2 H = __floats2half2_rn(a, b);
    float2 f = __half22float2(H);
    __half2 L = __floats2half2_rn(a - f.x, b - f.y);
    h = *reinterpret_cast<uint32_t*>(&H);
    l = *reinterpret_cast<uint32_t*>(&L);
}
__device__ __forceinline__ float tanh_ap(float x) {
    float r;
    asm("tanh.approx.f32 %0, %1;" : "=f"(r) : "f"(x));
    return r;
}

// D{0,1} = A{0,1}(hi) @ (Wh + Wl): each frag load feeds 4 MMAs.
__device__ __forceinline__ void gemm2blk(float* D, const uint32_t* AH,
                                         const char* Wf, int lane) {
#pragma unroll
    for (int i = 0; i < 64; ++i) D[i] = 0.0f;
#pragma unroll
    for (int j = 0; j < 8; ++j) {
#pragma unroll
        for (int kt = 0; kt < 4; ++kt) {
            uint4 f = *reinterpret_cast<const uint4*>(
                Wf + (((kt * 8 + j) * 32) + lane) * 16);
            mma8(D + 4*j,      AH[4*kt],    AH[4*kt+1],  AH[4*kt+2],  AH[4*kt+3],
                 f.x, f.y);
            mma8(D + 4*j,      AH[4*kt],    AH[4*kt+1],  AH[4*kt+2],  AH[4*kt+3],
                 f.z, f.w);
            mma8(D + 32 + 4*j, AH[16+4*kt], AH[16+4*kt+1], AH[16+4*kt+2],
                 AH[16+4*kt+3], f.x, f.y);
            mma8(D + 32 + 4*j, AH[16+4*kt], AH[16+4*kt+1], AH[16+4*kt+2],
                 AH[16+4*kt+3], f.z, f.w);
        }
    }
}

__global__ __launch_bounds__(LNN_NT, 2)
void lnn2276_v9_kernel(const float* __restrict__ x,
                       const float* __restrict__ ts,
                       const float* __restrict__ gWin, const float* __restrict__ gbin,
                       const float* __restrict__ gW1,  const float* __restrict__ gb1,
                       const float* __restrict__ gW2,  const float* __restrict__ gb2,
                       const float* __restrict__ gWout, const float* __restrict__ gbout,
                       float* __restrict__ out, int B) {
    extern __shared__ char sm[];
    const int tid  = threadIdx.x;
    const int w    = tid >> 5;
    const int lane = tid & 31;
    const int g    = lane >> 2;
    const int tig  = lane & 3;

    // ---- prologue: W fragments (hi/lo interleaved uint4) ----
    for (int p = tid; p < 1024; p += LNN_NT) {
        int kt = p >> 8, j = (p >> 5) & 7, ln = p & 31;
        int tg = ln & 3, gg = ln >> 2;
        int k0 = kt * 16 + 2 * tg;
        int n  = 8 * j + gg;
        float a0 = gW1[k0 * 64 + n],       a1 = gW1[(k0 + 1) * 64 + n];
        float a2 = gW1[(k0 + 8) * 64 + n], a3 = gW1[(k0 + 9) * 64 + n];
        uint32_t h0, l0, h1, l1;
        pack_hilo(a0, a1, h0, l0);
        pack_hilo(a2, a3, h1, l1);
        *reinterpret_cast<uint4*>(sm + OFF_W1 + p * 16) = make_uint4(h0, h1, l0, l1);
        a0 = gW2[k0 * 64 + n];       a1 = gW2[(k0 + 1) * 64 + n];
        a2 = gW2[(k0 + 8) * 64 + n]; a3 = gW2[(k0 + 9) * 64 + n];
        pack_hilo(a0, a1, h0, l0);
        pack_hilo(a2, a3, h1, l1);
        *reinterpret_cast<uint4*>(sm + OFF_W2 + p * 16) = make_uint4(h0, h1, l0, l1);
    }
    if (tid < 64) {
        *(float*)(sm + OFF_B1 + tid * 4) = gb1[tid];
        *(float*)(sm + OFF_B2 + tid * 4) = gb2[tid];
    }
    __syncthreads();

    const float dt = (ts[1] - ts[0]) * (1.0f / (float)LNN_NSTEPS);
    const uint32_t dt2 = packh2(dt, dt);
    const int rowbase = blockIdx.x * LNN_M + w * 32 + g;  // +blk*16, +8 for half

    // ---- y0 = x @ Win + bin (blk-major D-fragment layout, 64 values) ----
    float y[64];
#pragma unroll
    for (int blk = 0; blk < 2; ++blk) {
        const int r1 = rowbase + blk * 16;
        const int r2 = r1 + 8;
        float xr1[LNN_DIN], xr2[LNN_DIN];
#pragma unroll
        for (int k = 0; k < LNN_DIN; ++k) {
            xr1[k] = (r1 < B) ? __ldg(&x[(size_t)r1 * LNN_DIN + k]) : 0.0f;
            xr2[k] = (r2 < B) ? __ldg(&x[(size_t)r2 * LNN_DIN + k]) : 0.0f;
        }
#pragma unroll
        for (int j = 0; j < 8; ++j) {
            int c0 = 8 * j + 2 * tig;
            float s0 = __ldg(&gbin[c0]);
            float s1 = __ldg(&gbin[c0 + 1]);
            float a0 = s0, a1 = s1, a2 = s0, a3 = s1;
#pragma unroll
            for (int k = 0; k < LNN_DIN; ++k) {
                float w0 = __ldg(&gWin[k * 64 + c0]);
                float w1 = __ldg(&gWin[k * 64 + c0 + 1]);
                a0 = fmaf(xr1[k], w0, a0);
                a1 = fmaf(xr1[k], w1, a1);
                a2 = fmaf(xr2[k], w0, a2);
                a3 = fmaf(xr2[k], w1, a3);
            }
            y[blk*32 + 4*j + 0] = a0; y[blk*32 + 4*j + 1] = a1;
            y[blk*32 + 4*j + 2] = a2; y[blk*32 + 4*j + 3] = a3;
        }
    }

    // thread-private ACC slice: + m*16384 + blk*2048 + p*512
    char* accT = sm + OFF_ACC + (size_t)w * 4096 + (size_t)lane * 16;

    uint32_t accY[32];   // fp16 half2
    uint32_t AH[32];     // A frags for both blocks; reused as kh after GEMM2
    float D[64];

#pragma unroll 1
    for (int step = 0; step < LNN_NSTEPS; ++step) {
#pragma unroll 1
        for (int s = 0; s < 6; ++s) {
            // ---- u-build -> AH ----
            if (s == 0) {
#pragma unroll
                for (int i = 0; i < 32; ++i)
                    AH[i] = packh2(y[2*i], y[2*i + 1]);
            } else {
                const char* ab = accT + (s - 1) * 16384;
#pragma unroll
                for (int blk = 0; blk < 2; ++blk)
#pragma unroll
                    for (int p = 0; p < 4; ++p) {
                        uint4 a = *reinterpret_cast<const uint4*>(
                            ab + blk * 2048 + p * 512);
                        int hb = blk * 16 + 4 * p;
                        int yb = blk * 32 + 8 * p;
                        AH[hb + 0] = hfma2u(dt2, a.x, packh2(y[yb+0], y[yb+1]));
                        AH[hb + 1] = hfma2u(dt2, a.y, packh2(y[yb+2], y[yb+3]));
                        AH[hb + 2] = hfma2u(dt2, a.z, packh2(y[yb+4], y[yb+5]));
                        AH[hb + 3] = hfma2u(dt2, a.w, packh2(y[yb+6], y[yb+7]));
                    }
            }
            // ---- GEMM1 (both blocks), tanh ----
            gemm2blk(D, AH, sm + OFF_W1, lane);
#pragma unroll
            for (int blk = 0; blk < 2; ++blk)
#pragma unroll
                for (int j = 0; j < 8; ++j) {
                    float2 bb = *(const float2*)(sm + OFF_B1 + (8*j + 2*tig) * 4);
                    int db = blk * 32 + 4 * j;
                    float t0 = tanh_ap(D[db+0] + bb.x);
                    float t1 = tanh_ap(D[db+1] + bb.y);
                    float t2 = tanh_ap(D[db+2] + bb.x);
                    float t3 = tanh_ap(D[db+3] + bb.y);
                    int t4 = blk * 16 + 4 * (j >> 1) + 2 * (j & 1);
                    AH[t4]     = packh2(t0, t1);
                    AH[t4 + 1] = packh2(t2, t3);
                }
            // ---- GEMM2 + bias -> k (in D) ----
            gemm2blk(D, AH, sm + OFF_W2, lane);
#pragma unroll
            for (int blk = 0; blk < 2; ++blk)
#pragma unroll
                for (int j = 0; j < 8; ++j) {
                    float2 bb = *(const float2*)(sm + OFF_B2 + (8*j + 2*tig) * 4);
                    int db = blk * 32 + 4 * j;
                    D[db+0] += bb.x; D[db+1] += bb.y;
                    D[db+2] += bb.x; D[db+3] += bb.y;
                }
            // ---- kh (reuse AH) ----
#pragma unroll
            for (int i = 0; i < 32; ++i)
                AH[i] = packh2(D[2*i], D[2*i + 1]);
            // ---- accY (fp16) ; BC[1] == 0 -> skip s==1 ----
            if (s == 0) {
                uint32_t bc2 = packh2(BC[0], BC[0]);
#pragma unroll
                for (int i = 0; i < 32; ++i) accY[i] = hmul2u(bc2, AH[i]);
            } else if (s != 1) {
                uint32_t bc2 = packh2(BC[s], BC[s]);
#pragma unroll
                for (int i = 0; i < 32; ++i)
                    accY[i] = hfma2u(bc2, AH[i], accY[i]);
            }
            // ---- stage-combination arrays (fp16 HFMA2 RMW, predicated) ----
            if (s < 5) {
#pragma unroll
                for (int m = 0; m < 5; ++m) {
                    if (m >= s) {
                        float cf = CT2[s][m];
                        uint32_t c2 = packh2(cf, cf);
                        char* ab = accT + m * 16384;
#pragma unroll
                        for (int blk = 0; blk < 2; ++blk)
#pragma unroll
                            for (int p = 0; p < 4; ++p) {
                                char* ap = ab + blk * 2048 + p * 512;
                                int hb = blk * 16 + 4 * p;
                                uint4 a;
                                if (s == 0) {
                                    a.x = hmul2u(c2, AH[hb+0]);
                                    a.y = hmul2u(c2, AH[hb+1]);
                                    a.z = hmul2u(c2, AH[hb+2]);
                                    a.w = hmul2u(c2, AH[hb+3]);
                                } else {
                                    a = *reinterpret_cast<const uint4*>(ap);
                                    a.x = hfma2u(c2, AH[hb+0], a.x);
                                    a.y = hfma2u(c2, AH[hb+1], a.y);
                                    a.z = hfma2u(c2, AH[hb+2], a.z);
                                    a.w = hfma2u(c2, AH[hb+3], a.w);
                                }
                                *reinterpret_cast<uint4*>(ap) = a;
                            }
                    }
                }
            }
        }
        // ---- y += dt * accY ----
#pragma unroll
        for (int i = 0; i < 32; ++i) {
            float2 f = __half22float2(*reinterpret_cast<__half2*>(&accY[i]));
            y[2*i]     = fmaf(dt, f.x, y[2*i]);
            y[2*i + 1] = fmaf(dt, f.y, y[2*i + 1]);
        }
    }

    // ---- out = y @ Wout + bout (quad shfl reduction, per block) ----
#pragma unroll
    for (int blk = 0; blk < 2; ++blk) {
        float o1[LNN_DOUT] = {0.f, 0.f, 0.f};
        float o2[LNN_DOUT] = {0.f, 0.f, 0.f};
#pragma unroll
        for (int j = 0; j < 8; ++j) {
#pragma unroll
            for (int e = 0; e < 2; ++e) {
                int col = 8 * j + 2 * tig + e;
#pragma unroll
                for (int q = 0; q < LNN_DOUT; ++q) {
                    float wv = __ldg(&gWout[col * LNN_DOUT + q]);
                    o1[q] = fmaf(y[blk*32 + 4*j + e],     wv, o1[q]);
                    o2[q] = fmaf(y[blk*32 + 4*j + 2 + e], wv, o2[q]);
                }
            }
        }
#pragma unroll
        for (int q = 0; q < LNN_DOUT; ++q) {
            o1[q] += __shfl_xor_sync(0xffffffffu, o1[q], 1);
            o1[q] += __shfl_xor_sync(0xffffffffu, o1[q], 2);
            o2[q] += __shfl_xor_sync(0xffffffffu, o2[q], 1);
            o2[q] += __shfl_xor_sync(0xffffffffu, o2[q], 2);
        }
        if (tig == 0) {
            const int r1 = rowbase + blk * 16;
            const int r2 = r1 + 8;
#pragma unroll
            for (int q = 0; q < LNN_DOUT; ++q) {
                float bo = __ldg(&gbout[q]);
                if (r1 < B) out[(size_t)r1 * LNN_DOUT + q] = o1[q] + bo;
                if (r2 < B) out[(size_t)r2 * LNN_DOUT + q] = o2[q] + bo;
            }
        }
    }
}

extern "C" void kernel_launch(void* const* d_in, const int* in_sizes, int n_in,
                              void* d_out, int out_size) {
    const float* x    = (const float*)d_in[0];
    const float* ts   = (const float*)d_in[1];
    const float* Win  = (const float*)d_in[2];
    const float* bin  = (const float*)d_in[3];
    const float* W1   = (const float*)d_in[4];
    const float* b1   = (const float*)d_in[5];
    const float* W2   = (const float*)d_in[6];
    const float* b2   = (const float*)d_in[7];
    const float* Wout = (const float*)d_in[8];
    const float* bout = (const float*)d_in[9];
    float* out = (float*)d_out;

    int B = in_sizes[0] / LNN_DIN;
    cudaFuncSetAttribute(lnn2276_v9_kernel,
                         cudaFuncAttributeMaxDynamicSharedMemorySize, SMEM_SZ);
    int grid = (B + LNN_M - 1) / LNN_M;
    lnn2276_v9_kernel<<<grid, LNN_NT, SMEM_SZ>>>(x, ts, Win, bin, W1, b1, W2, b2,
                                                 Wout, bout, out, B);
}

// round 10
// speedup vs baseline: 1.5276x; 1.5276x over previous
#include <cuda_runtime.h>
#include <cuda_fp16.h>
#include <cstdint>

// ---------------------------------------------------------------------------
// LiquidNeuralNetwork via mma.sync HMMA, M=32 per warp (2x m16 blocks).
// 2-product GEMMs: Ah*(Wh+Wl), fp32 accum; each W fragment load feeds 4 MMAs.
// DOPRI5 via k-storage: stage s stores packed k_s (fp16) once in SMEM;
// stage inputs built on the fly (hfma2 chain); final y-update in fp32 from
// stored k's + k6 in registers. No accY registers, no RMW accumulators.
// CTA = 128 rows / 4 warps, 2 CTAs/SM.
// ---------------------------------------------------------------------------

#define LNN_DIN    14
#define LNN_DOUT   3
#define LNN_M      128
#define LNN_NT     128
#define LNN_NSTEPS 32

// SMEM byte offsets
#define OFF_W1   0            // [4kt][8j][32lane] uint4 {h01,h89,l01,l89} = 16KB
#define OFF_W2   16384
#define OFF_K    32768        // 5 k-arrays x 16KB: [m][w][blk][p][lane] uint4
#define OFF_B1   114688       // 64 f32
#define OFF_B2   114944
#define SMEM_SZ  115200

// DOPRI5 A-matrix: AC[s][i] = coeff of k_{i+1} in input of stage s (s=1..5)
static __device__ constexpr float AC[6][5] = {
    {0.f, 0.f, 0.f, 0.f, 0.f},
    {(float)(1.0/5.0), 0.f, 0.f, 0.f, 0.f},
    {(float)(3.0/40.0), (float)(9.0/40.0), 0.f, 0.f, 0.f},
    {(float)(44.0/45.0), (float)(-56.0/15.0), (float)(32.0/9.0), 0.f, 0.f},
    {(float)(19372.0/6561.0), (float)(-25360.0/2187.0),
     (float)(64448.0/6561.0), (float)(-212.0/729.0), 0.f},
    {(float)(9017.0/3168.0), (float)(-355.0/33.0), (float)(46732.0/5247.0),
     (float)(49.0/176.0), (float)(-5103.0/18656.0)},
};
// Final weights: BF[j] pairs with k-array j (k_{j+1}); BF5 with k6 (in regs)
static __device__ constexpr float BF[5] = {
    (float)(35.0/384.0), 0.f, (float)(500.0/1113.0), (float)(125.0/192.0),
    (float)(-2187.0/6784.0)};
#define BF5 ((float)(11.0/84.0))

__device__ __forceinline__ void mma8(float* d, uint32_t a0, uint32_t a1,
                                     uint32_t a2, uint32_t a3,
                                     uint32_t b0, uint32_t b1) {
    asm("mma.sync.aligned.m16n8k16.row.col.f32.f16.f16.f32 "
        "{%0,%1,%2,%3}, {%4,%5,%6,%7}, {%8,%9}, {%0,%1,%2,%3};"
        : "+f"(d[0]), "+f"(d[1]), "+f"(d[2]), "+f"(d[3])
        : "r"(a0), "r"(a1), "r"(a2), "r"(a3), "r"(b0), "r"(b1));
}

__device__ __forceinline__ uint32_t packh2(float a, float b) {
    __half2 h = __floats2half2_rn(a, b);
    return *reinterpret_cast<uint32_t*>(&h);
}
__device__ __forceinline__ uint32_t hfma2u(uint32_t a, uint32_t b, uint32_t c) {
    __half2 r = __hfma2(*reinterpret_cast<__half2*>(&a),
                        *reinterpret_cast<__half2*>(&b),
                        *reinterpret_cast<__half2*>(&c));
    return *reinterpret_cast<uint32_t*>(&r);
}
__device__ __forceinline__ float2 unpackh2(uint32_t u) {
    return __half22float2(*reinterpret_cast<__half2*>(&u));
}
__device__ __forceinline__ void pack_hilo(float a, float b,
                                          uint32_t& h, uint32_t& l) {
    __half2 H = __floats2half2_rn(a, b);
    float2 f = __half22float2(H);
    __half2 L = __floats2half2_rn(a - f.x, b - f.y);
    h = *reinterpret_cast<uint32_t*>(&H);
    l = *reinterpret_cast<uint32_t*>(&L);
}
__device__ __forceinline__ float tanh_ap(float x) {
    float r;
    asm("tanh.approx.f32 %0, %1;" : "=f"(r) : "f"(x));
    return r;
}

// D{0,1} = A{0,1}(hi) @ (Wh + Wl): each frag load feeds 4 MMAs.
__device__ __forceinline__ void gemm2blk(float* D, const uint32_t* AH,
                                         const char* Wf, int lane) {
#pragma unroll
    for (int i = 0; i < 64; ++i) D[i] = 0.0f;
#pragma unroll
    for (int j = 0; j < 8; ++j) {
#pragma unroll
        for (int kt = 0; kt < 4; ++kt) {
            uint4 f = *reinterpret_cast<const uint4*>(
                Wf + (((kt * 8 + j) * 32) + lane) * 16);
            mma8(D + 4*j,      AH[4*kt],    AH[4*kt+1],  AH[4*kt+2],  AH[4*kt+3],
                 f.x, f.y);
            mma8(D + 4*j,      AH[4*kt],    AH[4*kt+1],  AH[4*kt+2],  AH[4*kt+3],
                 f.z, f.w);
            mma8(D + 32 + 4*j, AH[16+4*kt], AH[16+4*kt+1], AH[16+4*kt+2],
                 AH[16+4*kt+3], f.x, f.y);
            mma8(D + 32 + 4*j, AH[16+4*kt], AH[16+4*kt+1], AH[16+4*kt+2],
                 AH[16+4*kt+3], f.z, f.w);
        }
    }
}

__global__ __launch_bounds__(LNN_NT, 2)
void lnn2276_v10_kernel(const float* __restrict__ x,
                        const float* __restrict__ ts,
                        const float* __restrict__ gWin, const float* __restrict__ gbin,
                        const float* __restrict__ gW1,  const float* __restrict__ gb1,
                        const float* __restrict__ gW2,  const float* __restrict__ gb2,
                        const float* __restrict__ gWout, const float* __restrict__ gbout,
                        float* __restrict__ out, int B) {
    extern __shared__ char sm[];
    const int tid  = threadIdx.x;
    const int w    = tid >> 5;
    const int lane = tid & 31;
    const int g    = lane >> 2;
    const int tig  = lane & 3;

    // ---- prologue: W fragments (hi/lo interleaved uint4) ----
    for (int p = tid; p < 1024; p += LNN_NT) {
        int kt = p >> 8, j = (p >> 5) & 7, ln = p & 31;
        int tg = ln & 3, gg = ln >> 2;
        int k0 = kt * 16 + 2 * tg;
        int n  = 8 * j + gg;
        float a0 = gW1[k0 * 64 + n],       a1 = gW1[(k0 + 1) * 64 + n];
        float a2 = gW1[(k0 + 8) * 64 + n], a3 = gW1[(k0 + 9) * 64 + n];
        uint32_t h0, l0, h1, l1;
        pack_hilo(a0, a1, h0, l0);
        pack_hilo(a2, a3, h1, l1);
        *reinterpret_cast<uint4*>(sm + OFF_W1 + p * 16) = make_uint4(h0, h1, l0, l1);
        a0 = gW2[k0 * 64 + n];       a1 = gW2[(k0 + 1) * 64 + n];
        a2 = gW2[(k0 + 8) * 64 + n]; a3 = gW2[(k0 + 9) * 64 + n];
        pack_hilo(a0, a1, h0, l0);
        pack_hilo(a2, a3, h1, l1);
        *reinterpret_cast<uint4*>(sm + OFF_W2 + p * 16) = make_uint4(h0, h1, l0, l1);
    }
    if (tid < 64) {
        *(float*)(sm + OFF_B1 + tid * 4) = gb1[tid];
        *(float*)(sm + OFF_B2 + tid * 4) = gb2[tid];
    }
    __syncthreads();

    const float dt = (ts[1] - ts[0]) * (1.0f / (float)LNN_NSTEPS);
    const int rowbase = blockIdx.x * LNN_M + w * 32 + g;  // +blk*16, +8 for half

    // ---- y0 = x @ Win + bin (blk-major D-fragment layout, 64 values) ----
    float y[64];
#pragma unroll
    for (int blk = 0; blk < 2; ++blk) {
        const int r1 = rowbase + blk * 16;
        const int r2 = r1 + 8;
        float xr1[LNN_DIN], xr2[LNN_DIN];
#pragma unroll
        for (int k = 0; k < LNN_DIN; ++k) {
            xr1[k] = (r1 < B) ? __ldg(&x[(size_t)r1 * LNN_DIN + k]) : 0.0f;
            xr2[k] = (r2 < B) ? __ldg(&x[(size_t)r2 * LNN_DIN + k]) : 0.0f;
        }
#pragma unroll
        for (int j = 0; j < 8; ++j) {
            int c0 = 8 * j + 2 * tig;
            float s0 = __ldg(&gbin[c0]);
            float s1 = __ldg(&gbin[c0 + 1]);
            float a0 = s0, a1 = s1, a2 = s0, a3 = s1;
#pragma unroll
            for (int k = 0; k < LNN_DIN; ++k) {
                float w0 = __ldg(&gWin[k * 64 + c0]);
                float w1 = __ldg(&gWin[k * 64 + c0 + 1]);
                a0 = fmaf(xr1[k], w0, a0);
                a1 = fmaf(xr1[k], w1, a1);
                a2 = fmaf(xr2[k], w0, a2);
                a3 = fmaf(xr2[k], w1, a3);
            }
            y[blk*32 + 4*j + 0] = a0; y[blk*32 + 4*j + 1] = a1;
            y[blk*32 + 4*j + 2] = a2; y[blk*32 + 4*j + 3] = a3;
        }
    }

    // thread-private k slice: + m*16384 + blk*2048 + p*512
    char* kT = sm + OFF_K + (size_t)w * 4096 + (size_t)lane * 16;

    uint32_t AH[32];     // A frags for both blocks (fp16 half2)
    float D[64];

#pragma unroll 1
    for (int step = 0; step < LNN_NSTEPS; ++step) {
#pragma unroll 1
        for (int s = 0; s < 6; ++s) {
            // ---- u-build -> AH : u = y + dt * sum_i AC[s][i] * k_i ----
#pragma unroll
            for (int i = 0; i < 32; ++i)
                AH[i] = packh2(y[2*i], y[2*i + 1]);
#pragma unroll 1
            for (int i = 0; i < s; ++i) {
                float cf = dt * AC[s][i];
                uint32_t c2 = packh2(cf, cf);
                const char* ab = kT + i * 16384;
#pragma unroll
                for (int blk = 0; blk < 2; ++blk)
#pragma unroll
                    for (int p = 0; p < 4; ++p) {
                        uint4 a = *reinterpret_cast<const uint4*>(
                            ab + blk * 2048 + p * 512);
                        int hb = blk * 16 + 4 * p;
                        AH[hb + 0] = hfma2u(c2, a.x, AH[hb + 0]);
                        AH[hb + 1] = hfma2u(c2, a.y, AH[hb + 1]);
                        AH[hb + 2] = hfma2u(c2, a.z, AH[hb + 2]);
                        AH[hb + 3] = hfma2u(c2, a.w, AH[hb + 3]);
                    }
            }
            // ---- GEMM1 (both blocks), tanh ----
            gemm2blk(D, AH, sm + OFF_W1, lane);
#pragma unroll
            for (int blk = 0; blk < 2; ++blk)
#pragma unroll
                for (int j = 0; j < 8; ++j) {
                    float2 bb = *(const float2*)(sm + OFF_B1 + (8*j + 2*tig) * 4);
                    int db = blk * 32 + 4 * j;
                    float t0 = tanh_ap(D[db+0] + bb.x);
                    float t1 = tanh_ap(D[db+1] + bb.y);
                    float t2 = tanh_ap(D[db+2] + bb.x);
                    float t3 = tanh_ap(D[db+3] + bb.y);
                    int t4 = blk * 16 + 4 * (j >> 1) + 2 * (j & 1);
                    AH[t4]     = packh2(t0, t1);
                    AH[t4 + 1] = packh2(t2, t3);
                }
            // ---- GEMM2 + bias -> k (in D) ----
            gemm2blk(D, AH, sm + OFF_W2, lane);
#pragma unroll
            for (int blk = 0; blk < 2; ++blk)
#pragma unroll
                for (int j = 0; j < 8; ++j) {
                    float2 bb = *(const float2*)(sm + OFF_B2 + (8*j + 2*tig) * 4);
                    int db = blk * 32 + 4 * j;
                    D[db+0] += bb.x; D[db+1] += bb.y;
                    D[db+2] += bb.x; D[db+3] += bb.y;
                }
            // ---- store packed k_s (s<5); k6 stays in D ----
            if (s < 5) {
                char* ab = kT + s * 16384;
#pragma unroll
                for (int blk = 0; blk < 2; ++blk)
#pragma unroll
                    for (int p = 0; p < 4; ++p) {
                        int yb = blk * 32 + 8 * p;
                        uint4 a;
                        a.x = packh2(D[yb+0], D[yb+1]);
                        a.y = packh2(D[yb+2], D[yb+3]);
                        a.z = packh2(D[yb+4], D[yb+5]);
                        a.w = packh2(D[yb+6], D[yb+7]);
                        *reinterpret_cast<uint4*>(ab + blk * 2048 + p * 512) = a;
                    }
            }
        }
        // ---- y += dt*(B1 k1 + B3 k3 + B4 k4 + B5 k5 + B6 k6) in fp32 ----
#pragma unroll
        for (int i = 0; i < 64; ++i)
            y[i] = fmaf(dt * BF5, D[i], y[i]);
#pragma unroll 1
        for (int m = 0; m < 5; ++m) {
            if (m == 1) continue;  // B2 == 0
            float cf = dt * BF[m];
            const char* ab = kT + m * 16384;
#pragma unroll
            for (int blk = 0; blk < 2; ++blk)
#pragma unroll
                for (int p = 0; p < 4; ++p) {
                    uint4 a = *reinterpret_cast<const uint4*>(
                        ab + blk * 2048 + p * 512);
                    int yb = blk * 32 + 8 * p;
                    float2 f0 = unpackh2(a.x);
                    float2 f1 = unpackh2(a.y);
                    float2 f2 = unpackh2(a.z);
                    float2 f3 = unpackh2(a.w);
                    y[yb+0] = fmaf(cf, f0.x, y[yb+0]);
                    y[yb+1] = fmaf(cf, f0.y, y[yb+1]);
                    y[yb+2] = fmaf(cf, f1.x, y[yb+2]);
                    y[yb+3] = fmaf(cf, f1.y, y[yb+3]);
                    y[yb+4] = fmaf(cf, f2.x, y[yb+4]);
                    y[yb+5] = fmaf(cf, f2.y, y[yb+5]);
                    y[yb+6] = fmaf(cf, f3.x, y[yb+6]);
                    y[yb+7] = fmaf(cf, f3.y, y[yb+7]);
                }
        }
    }

    // ---- out = y @ Wout + bout (quad shfl reduction, per block) ----
#pragma unroll
    for (int blk = 0; blk < 2; ++blk) {
        float o1[LNN_DOUT] = {0.f, 0.f, 0.f};
        float o2[LNN_DOUT] = {0.f, 0.f, 0.f};
#pragma unroll
        for (int j = 0; j < 8; ++j) {
#pragma unroll
            for (int e = 0; e < 2; ++e) {
                int col = 8 * j + 2 * tig + e;
#pragma unroll
                for (int q = 0; q < LNN_DOUT; ++q) {
                    float wv = __ldg(&gWout[col * LNN_DOUT + q]);
                    o1[q] = fmaf(y[blk*32 + 4*j + e],     wv, o1[q]);
                    o2[q] = fmaf(y[blk*32 + 4*j + 2 + e], wv, o2[q]);
                }
            }
        }
#pragma unroll
        for (int q = 0; q < LNN_DOUT; ++q) {
            o1[q] += __shfl_xor_sync(0xffffffffu, o1[q], 1);
            o1[q] += __shfl_xor_sync(0xffffffffu, o1[q], 2);
            o2[q] += __shfl_xor_sync(0xffffffffu, o2[q], 1);
            o2[q] += __shfl_xor_sync(0xffffffffu, o2[q], 2);
        }
        if (tig == 0) {
            const int r1 = rowbase + blk * 16;
            const int r2 = r1 + 8;
#pragma unroll
            for (int q = 0; q < LNN_DOUT; ++q) {
                float bo = __ldg(&gbout[q]);
                if (r1 < B) out[(size_t)r1 * LNN_DOUT + q] = o1[q] + bo;
                if (r2 < B) out[(size_t)r2 * LNN_DOUT + q] = o2[q] + bo;
            }
        }
    }
}

extern "C" void kernel_launch(void* const* d_in, const int* in_sizes, int n_in,
                              void* d_out, int out_size) {
    const float* x    = (const float*)d_in[0];
    const float* ts   = (const float*)d_in[1];
    const float* Win  = (const float*)d_in[2];
    const float* bin  = (const float*)d_in[3];
    const float* W1   = (const float*)d_in[4];
    const float* b1   = (const float*)d_in[5];
    const float* W2   = (const float*)d_in[6];
    const float* b2   = (const float*)d_in[7];
    const float* Wout = (const float*)d_in[8];
    const float* bout = (const float*)d_in[9];
    float* out = (float*)d_out;

    int B = in_sizes[0] / LNN_DIN;
    cudaFuncSetAttribute(lnn2276_v10_kernel,
                         cudaFuncAttributeMaxDynamicSharedMemorySize, SMEM_SZ);
    int grid = (B + LNN_M - 1) / LNN_M;
    lnn2276_v10_kernel<<<grid, LNN_NT, SMEM_SZ>>>(x, ts, Win, bin, W1, b1, W2, b2,
                                                  Wout, bout, out, B);
}

// round 11
// speedup vs baseline: 2.3751x; 1.5548x over previous
#include <cuda_runtime.h>
#include <cuda_fp16.h>
#include <cstdint>

// ---------------------------------------------------------------------------
// LiquidNeuralNetwork via mma.sync HMMA, M=32 per warp (2x m16 blocks).
// SINGLE-product GEMMs: A(fp16) @ W(fp16), fp32 accum. W frags packed two
// kt-steps per uint4 -> 16 LDS.128 + 64 MMA per GEMM per warp.
// DOPRI5 via k-storage: stage s stores packed k_s (fp16) once in SMEM;
// stage inputs built on the fly (hfma2 chain); final y-update in fp32.
// CTA = 128 rows / 4 warps, 2 CTAs/SM.
// ---------------------------------------------------------------------------

#define LNN_DIN    14
#define LNN_DOUT   3
#define LNN_M      128
#define LNN_NT     128
#define LNN_NSTEPS 32

// SMEM byte offsets
#define OFF_W1   0            // [2ktp][8j][32lane] uint4 {h01,h89 | kt, kt+1} = 8KB
#define OFF_W2   8192
#define OFF_K    16384        // 5 k-arrays x 16KB: [m][w][blk][p][lane] uint4
#define OFF_B1   98304        // 64 f32
#define OFF_B2   98560
#define SMEM_SZ  98816

// DOPRI5 A-matrix: AC[s][i] = coeff of k_{i+1} in input of stage s (s=1..5)
static __device__ constexpr float AC[6][5] = {
    {0.f, 0.f, 0.f, 0.f, 0.f},
    {(float)(1.0/5.0), 0.f, 0.f, 0.f, 0.f},
    {(float)(3.0/40.0), (float)(9.0/40.0), 0.f, 0.f, 0.f},
    {(float)(44.0/45.0), (float)(-56.0/15.0), (float)(32.0/9.0), 0.f, 0.f},
    {(float)(19372.0/6561.0), (float)(-25360.0/2187.0),
     (float)(64448.0/6561.0), (float)(-212.0/729.0), 0.f},
    {(float)(9017.0/3168.0), (float)(-355.0/33.0), (float)(46732.0/5247.0),
     (float)(49.0/176.0), (float)(-5103.0/18656.0)},
};
// Final weights: BF[j] pairs with k-array j (k_{j+1}); BF5 with k6 (in regs)
static __device__ constexpr float BF[5] = {
    (float)(35.0/384.0), 0.f, (float)(500.0/1113.0), (float)(125.0/192.0),
    (float)(-2187.0/6784.0)};
#define BF5 ((float)(11.0/84.0))

__device__ __forceinline__ void mma8(float* d, uint32_t a0, uint32_t a1,
                                     uint32_t a2, uint32_t a3,
                                     uint32_t b0, uint32_t b1) {
    asm("mma.sync.aligned.m16n8k16.row.col.f32.f16.f16.f32 "
        "{%0,%1,%2,%3}, {%4,%5,%6,%7}, {%8,%9}, {%0,%1,%2,%3};"
        : "+f"(d[0]), "+f"(d[1]), "+f"(d[2]), "+f"(d[3])
        : "r"(a0), "r"(a1), "r"(a2), "r"(a3), "r"(b0), "r"(b1));
}

__device__ __forceinline__ uint32_t packh2(float a, float b) {
    __half2 h = __floats2half2_rn(a, b);
    return *reinterpret_cast<uint32_t*>(&h);
}
__device__ __forceinline__ uint32_t hfma2u(uint32_t a, uint32_t b, uint32_t c) {
    __half2 r = __hfma2(*reinterpret_cast<__half2*>(&a),
                        *reinterpret_cast<__half2*>(&b),
                        *reinterpret_cast<__half2*>(&c));
    return *reinterpret_cast<uint32_t*>(&r);
}
__device__ __forceinline__ float2 unpackh2(uint32_t u) {
    return __half22float2(*reinterpret_cast<__half2*>(&u));
}
__device__ __forceinline__ float tanh_ap(float x) {
    float r;
    asm("tanh.approx.f32 %0, %1;" : "=f"(r) : "f"(x));
    return r;
}

// D{0,1} = A{0,1}(fp16) @ W(fp16): one product; 2 kt-frags per W load.
__device__ __forceinline__ void gemm1p(float* D, const uint32_t* AH,
                                       const char* Wf, int lane) {
#pragma unroll
    for (int i = 0; i < 64; ++i) D[i] = 0.0f;
#pragma unroll
    for (int j = 0; j < 8; ++j) {
#pragma unroll
        for (int ktp = 0; ktp < 2; ++ktp) {
            uint4 f = *reinterpret_cast<const uint4*>(
                Wf + (((ktp * 8 + j) * 32) + lane) * 16);
            // kt = 2*ktp : frag (f.x, f.y); kt = 2*ktp+1 : frag (f.z, f.w)
            mma8(D + 4*j,      AH[8*ktp+0],  AH[8*ktp+1],  AH[8*ktp+2],
                 AH[8*ktp+3],  f.x, f.y);
            mma8(D + 4*j,      AH[8*ktp+4],  AH[8*ktp+5],  AH[8*ktp+6],
                 AH[8*ktp+7],  f.z, f.w);
            mma8(D + 32 + 4*j, AH[16+8*ktp+0], AH[16+8*ktp+1], AH[16+8*ktp+2],
                 AH[16+8*ktp+3], f.x, f.y);
            mma8(D + 32 + 4*j, AH[16+8*ktp+4], AH[16+8*ktp+5], AH[16+8*ktp+6],
                 AH[16+8*ktp+7], f.z, f.w);
        }
    }
}

__global__ __launch_bounds__(LNN_NT, 2)
void lnn2276_v11_kernel(const float* __restrict__ x,
                        const float* __restrict__ ts,
                        const float* __restrict__ gWin, const float* __restrict__ gbin,
                        const float* __restrict__ gW1,  const float* __restrict__ gb1,
                        const float* __restrict__ gW2,  const float* __restrict__ gb2,
                        const float* __restrict__ gWout, const float* __restrict__ gbout,
                        float* __restrict__ out, int B) {
    extern __shared__ char sm[];
    const int tid  = threadIdx.x;
    const int w    = tid >> 5;
    const int lane = tid & 31;
    const int g    = lane >> 2;
    const int tig  = lane & 3;

    // ---- prologue: W fragments, 2 kt per uint4 ----
    for (int p = tid; p < 512; p += LNN_NT) {
        int ktp = p >> 8, j = (p >> 5) & 7, ln = p & 31;
        int tg = ln & 3, gg = ln >> 2;
        int n  = 8 * j + gg;
        uint32_t v[2][2];
#pragma unroll
        for (int e = 0; e < 2; ++e) {           // e: which kt of the pair
            int k0 = (2 * ktp + e) * 16 + 2 * tg;
            v[e][0] = packh2(gW1[k0 * 64 + n],       gW1[(k0 + 1) * 64 + n]);
            v[e][1] = packh2(gW1[(k0 + 8) * 64 + n], gW1[(k0 + 9) * 64 + n]);
        }
        *reinterpret_cast<uint4*>(sm + OFF_W1 + p * 16) =
            make_uint4(v[0][0], v[0][1], v[1][0], v[1][1]);
#pragma unroll
        for (int e = 0; e < 2; ++e) {
            int k0 = (2 * ktp + e) * 16 + 2 * tg;
            v[e][0] = packh2(gW2[k0 * 64 + n],       gW2[(k0 + 1) * 64 + n]);
            v[e][1] = packh2(gW2[(k0 + 8) * 64 + n], gW2[(k0 + 9) * 64 + n]);
        }
        *reinterpret_cast<uint4*>(sm + OFF_W2 + p * 16) =
            make_uint4(v[0][0], v[0][1], v[1][0], v[1][1]);
    }
    if (tid < 64) {
        *(float*)(sm + OFF_B1 + tid * 4) = gb1[tid];
        *(float*)(sm + OFF_B2 + tid * 4) = gb2[tid];
    }
    __syncthreads();

    const float dt = (ts[1] - ts[0]) * (1.0f / (float)LNN_NSTEPS);
    const int rowbase = blockIdx.x * LNN_M + w * 32 + g;  // +blk*16, +8 for half

    // ---- y0 = x @ Win + bin (blk-major D-fragment layout, 64 values) ----
    float y[64];
#pragma unroll
    for (int blk = 0; blk < 2; ++blk) {
        const int r1 = rowbase + blk * 16;
        const int r2 = r1 + 8;
        float xr1[LNN_DIN], xr2[LNN_DIN];
#pragma unroll
        for (int k = 0; k < LNN_DIN; ++k) {
            xr1[k] = (r1 < B) ? __ldg(&x[(size_t)r1 * LNN_DIN + k]) : 0.0f;
            xr2[k] = (r2 < B) ? __ldg(&x[(size_t)r2 * LNN_DIN + k]) : 0.0f;
        }
#pragma unroll
        for (int j = 0; j < 8; ++j) {
            int c0 = 8 * j + 2 * tig;
            float s0 = __ldg(&gbin[c0]);
            float s1 = __ldg(&gbin[c0 + 1]);
            float a0 = s0, a1 = s1, a2 = s0, a3 = s1;
#pragma unroll
            for (int k = 0; k < LNN_DIN; ++k) {
                float w0 = __ldg(&gWin[k * 64 + c0]);
                float w1 = __ldg(&gWin[k * 64 + c0 + 1]);
                a0 = fmaf(xr1[k], w0, a0);
                a1 = fmaf(xr1[k], w1, a1);
                a2 = fmaf(xr2[k], w0, a2);
                a3 = fmaf(xr2[k], w1, a3);
            }
            y[blk*32 + 4*j + 0] = a0; y[blk*32 + 4*j + 1] = a1;
            y[blk*32 + 4*j + 2] = a2; y[blk*32 + 4*j + 3] = a3;
        }
    }

    // thread-private k slice: + m*16384 + blk*2048 + p*512
    char* kT = sm + OFF_K + (size_t)w * 4096 + (size_t)lane * 16;

    uint32_t AH[32];     // A frags for both blocks (fp16 half2)
    float D[64];

#pragma unroll 1
    for (int step = 0; step < LNN_NSTEPS; ++step) {
#pragma unroll 1
        for (int s = 0; s < 6; ++s) {
            // ---- u-build -> AH : u = y + dt * sum_i AC[s][i] * k_i ----
#pragma unroll
            for (int i = 0; i < 32; ++i)
                AH[i] = packh2(y[2*i], y[2*i + 1]);
#pragma unroll 1
            for (int i = 0; i < s; ++i) {
                float cf = dt * AC[s][i];
                uint32_t c2 = packh2(cf, cf);
                const char* ab = kT + i * 16384;
#pragma unroll
                for (int blk = 0; blk < 2; ++blk)
#pragma unroll
                    for (int p = 0; p < 4; ++p) {
                        uint4 a = *reinterpret_cast<const uint4*>(
                            ab + blk * 2048 + p * 512);
                        int hb = blk * 16 + 4 * p;
                        AH[hb + 0] = hfma2u(c2, a.x, AH[hb + 0]);
                        AH[hb + 1] = hfma2u(c2, a.y, AH[hb + 1]);
                        AH[hb + 2] = hfma2u(c2, a.z, AH[hb + 2]);
                        AH[hb + 3] = hfma2u(c2, a.w, AH[hb + 3]);
                    }
            }
            // ---- GEMM1 (both blocks), tanh ----
            gemm1p(D, AH, sm + OFF_W1, lane);
#pragma unroll
            for (int blk = 0; blk < 2; ++blk)
#pragma unroll
                for (int j = 0; j < 8; ++j) {
                    float2 bb = *(const float2*)(sm + OFF_B1 + (8*j + 2*tig) * 4);
                    int db = blk * 32 + 4 * j;
                    float t0 = tanh_ap(D[db+0] + bb.x);
                    float t1 = tanh_ap(D[db+1] + bb.y);
                    float t2 = tanh_ap(D[db+2] + bb.x);
                    float t3 = tanh_ap(D[db+3] + bb.y);
                    int t4 = blk * 16 + 4 * (j >> 1) + 2 * (j & 1);
                    AH[t4]     = packh2(t0, t1);
                    AH[t4 + 1] = packh2(t2, t3);
                }
            // ---- GEMM2 + bias -> k (in D) ----
            gemm1p(D, AH, sm + OFF_W2, lane);
#pragma unroll
            for (int blk = 0; blk < 2; ++blk)
#pragma unroll
                for (int j = 0; j < 8; ++j) {
                    float2 bb = *(const float2*)(sm + OFF_B2 + (8*j + 2*tig) * 4);
                    int db = blk * 32 + 4 * j;
                    D[db+0] += bb.x; D[db+1] += bb.y;
                    D[db+2] += bb.x; D[db+3] += bb.y;
                }
            // ---- store packed k_s (s<5); k6 stays in D ----
            if (s < 5) {
                char* ab = kT + s * 16384;
#pragma unroll
                for (int blk = 0; blk < 2; ++blk)
#pragma unroll
                    for (int p = 0; p < 4; ++p) {
                        int yb = blk * 32 + 8 * p;
                        uint4 a;
                        a.x = packh2(D[yb+0], D[yb+1]);
                        a.y = packh2(D[yb+2], D[yb+3]);
                        a.z = packh2(D[yb+4], D[yb+5]);
                        a.w = packh2(D[yb+6], D[yb+7]);
                        *reinterpret_cast<uint4*>(ab + blk * 2048 + p * 512) = a;
                    }
            }
        }
        // ---- y += dt*(B1 k1 + B3 k3 + B4 k4 + B5 k5 + B6 k6) in fp32 ----
#pragma unroll
        for (int i = 0; i < 64; ++i)
            y[i] = fmaf(dt * BF5, D[i], y[i]);
#pragma unroll 1
        for (int m = 0; m < 5; ++m) {
            if (m == 1) continue;  // B2 == 0
            float cf = dt * BF[m];
            const char* ab = kT + m * 16384;
#pragma unroll
            for (int blk = 0; blk < 2; ++blk)
#pragma unroll
                for (int p = 0; p < 4; ++p) {
                    uint4 a = *reinterpret_cast<const uint4*>(
                        ab + blk * 2048 + p * 512);
                    int yb = blk * 32 + 8 * p;
                    float2 f0 = unpackh2(a.x);
                    float2 f1 = unpackh2(a.y);
                    float2 f2 = unpackh2(a.z);
                    float2 f3 = unpackh2(a.w);
                    y[yb+0] = fmaf(cf, f0.x, y[yb+0]);
                    y[yb+1] = fmaf(cf, f0.y, y[yb+1]);
                    y[yb+2] = fmaf(cf, f1.x, y[yb+2]);
                    y[yb+3] = fmaf(cf, f1.y, y[yb+3]);
                    y[yb+4] = fmaf(cf, f2.x, y[yb+4]);
                    y[yb+5] = fmaf(cf, f2.y, y[yb+5]);
                    y[yb+6] = fmaf(cf, f3.x, y[yb+6]);
                    y[yb+7] = fmaf(cf, f3.y, y[yb+7]);
                }
        }
    }

    // ---- out = y @ Wout + bout (quad shfl reduction, per block) ----
#pragma unroll
    for (int blk = 0; blk < 2; ++blk) {
        float o1[LNN_DOUT] = {0.f, 0.f, 0.f};
        float o2[LNN_DOUT] = {0.f, 0.f, 0.f};
#pragma unroll
        for (int j = 0; j < 8; ++j) {
#pragma unroll
            for (int e = 0; e < 2; ++e) {
                int col = 8 * j + 2 * tig + e;
#pragma unroll
                for (int q = 0; q < LNN_DOUT; ++q) {
                    float wv = __ldg(&gWout[col * LNN_DOUT + q]);
                    o1[q] = fmaf(y[blk*32 + 4*j + e],     wv, o1[q]);
                    o2[q] = fmaf(y[blk*32 + 4*j + 2 + e], wv, o2[q]);
                }
            }
        }
#pragma unroll
        for (int q = 0; q < LNN_DOUT; ++q) {
            o1[q] += __shfl_xor_sync(0xffffffffu, o1[q], 1);
            o1[q] += __shfl_xor_sync(0xffffffffu, o1[q], 2);
            o2[q] += __shfl_xor_sync(0xffffffffu, o2[q], 1);
            o2[q] += __shfl_xor_sync(0xffffffffu, o2[q], 2);
        }
        if (tig == 0) {
            const int r1 = rowbase + blk * 16;
            const int r2 = r1 + 8;
#pragma unroll
            for (int q = 0; q < LNN_DOUT; ++q) {
                float bo = __ldg(&gbout[q]);
                if (r1 < B) out[(size_t)r1 * LNN_DOUT + q] = o1[q] + bo;
                if (r2 < B) out[(size_t)r2 * LNN_DOUT + q] = o2[q] + bo;
            }
        }
    }
}

extern "C" void kernel_launch(void* const* d_in, const int* in_sizes, int n_in,
                              void* d_out, int out_size) {
    const float* x    = (const float*)d_in[0];
    const float* ts   = (const float*)d_in[1];
    const float* Win  = (const float*)d_in[2];
    const float* bin  = (const float*)d_in[3];
    const float* W1   = (const float*)d_in[4];
    const float* b1   = (const float*)d_in[5];
    const float* W2   = (const float*)d_in[6];
    const float* b2   = (const float*)d_in[7];
    const float* Wout = (const float*)d_in[8];
    const float* bout = (const float*)d_in[9];
    float* out = (float*)d_out;

    int B = in_sizes[0] / LNN_DIN;
    cudaFuncSetAttribute(lnn2276_v11_kernel,
                         cudaFuncAttributeMaxDynamicSharedMemorySize, SMEM_SZ);
    int grid = (B + LNN_M - 1) / LNN_M;
    lnn2276_v11_kernel<<<grid, LNN_NT, SMEM_SZ>>>(x, ts, Win, bin, W1, b1, W2, b2,
                                                  Wout, bout, out, B);
}

// round 12
// speedup vs baseline: 2.6304x; 1.1075x over previous
#include <cuda_runtime.h>
#include <cuda_fp16.h>
#include <cstdint>

// ---------------------------------------------------------------------------
// LiquidNeuralNetwork via mma.sync HMMA, M=32 per warp (2x m16 blocks).
// Single-product GEMMs A(fp16)@W(fp16), fp32 accum, bias folded into D-init.
// DOPRI5 incremental-fold: y += dt*b_s*k_s in fp32 per stage (k_s in regs);
// stage inputs rebased v_s = Y_{s-2} + dt*sum (a_si - b_i) k_i + dt*a_{s,s-1}*D.
// Only k1..k4 stored (fp16, 4 arrays); k5/k6 consumed from registers.
// CTA = 128 rows / 4 warps, 2 CTAs/SM.
// ---------------------------------------------------------------------------

#define LNN_DIN    14
#define LNN_DOUT   3
#define LNN_M      128
#define LNN_NT     128
#define LNN_NSTEPS 32

// SMEM byte offsets
#define OFF_W1   0            // [2ktp][8j][32lane] uint4 = 8KB
#define OFF_W2   8192
#define OFF_K    16384        // 4 k-arrays x 16KB: [m][w][blk][p][lane] uint4
#define OFF_B1   81920        // 64 f32
#define OFF_B2   82176
#define SMEM_SZ  82432

// gamma: GAM[s] = a_{s+1,s} (coeff of k_s from D regs in stage s+1 input)
static __device__ constexpr float GAM[6] = {
    0.f, (float)(1.0/5.0), (float)(9.0/40.0), (float)(32.0/9.0),
    (float)(-212.0/729.0), (float)(-5103.0/18656.0)};
// ACB[s][i] = a_{s+1,i+1} - b_{i+1}  (array terms, rebased)
static __device__ constexpr float ACB[6][4] = {
    {0.f, 0.f, 0.f, 0.f},
    {0.f, 0.f, 0.f, 0.f},
    {(float)(3.0/40.0 - 35.0/384.0), 0.f, 0.f, 0.f},
    {(float)(44.0/45.0 - 35.0/384.0), (float)(-56.0/15.0), 0.f, 0.f},
    {(float)(19372.0/6561.0 - 35.0/384.0), (float)(-25360.0/2187.0),
     (float)(64448.0/6561.0 - 500.0/1113.0), 0.f},
    {(float)(9017.0/3168.0 - 35.0/384.0), (float)(-355.0/33.0),
     (float)(46732.0/5247.0 - 500.0/1113.0), (float)(49.0/176.0 - 125.0/192.0)},
};
// Bb[s-1] = b_s (fold coefficient when D = k_s)
static __device__ constexpr float Bb[6] = {
    (float)(35.0/384.0), 0.f, (float)(500.0/1113.0), (float)(125.0/192.0),
    (float)(-2187.0/6784.0), (float)(11.0/84.0)};

__device__ __forceinline__ void mma8(float* d, uint32_t a0, uint32_t a1,
                                     uint32_t a2, uint32_t a3,
                                     uint32_t b0, uint32_t b1) {
    asm("mma.sync.aligned.m16n8k16.row.col.f32.f16.f16.f32 "
        "{%0,%1,%2,%3}, {%4,%5,%6,%7}, {%8,%9}, {%0,%1,%2,%3};"
        : "+f"(d[0]), "+f"(d[1]), "+f"(d[2]), "+f"(d[3])
        : "r"(a0), "r"(a1), "r"(a2), "r"(a3), "r"(b0), "r"(b1));
}

__device__ __forceinline__ uint32_t packh2(float a, float b) {
    __half2 h = __floats2half2_rn(a, b);
    return *reinterpret_cast<uint32_t*>(&h);
}
__device__ __forceinline__ uint32_t hfma2u(uint32_t a, uint32_t b, uint32_t c) {
    __half2 r = __hfma2(*reinterpret_cast<__half2*>(&a),
                        *reinterpret_cast<__half2*>(&b),
                        *reinterpret_cast<__half2*>(&c));
    return *reinterpret_cast<uint32_t*>(&r);
}
__device__ __forceinline__ float tanh_ap(float x) {
    float r;
    asm("tanh.approx.f32 %0, %1;" : "=f"(r) : "f"(x));
    return r;
}

// D{0,1} = bias + A{0,1}(fp16) @ W(fp16): bias-initialized, one product.
__device__ __forceinline__ void gemm1p(float* D, const uint32_t* AH,
                                       const char* Wf, const char* bias,
                                       int lane, int tig) {
#pragma unroll
    for (int j = 0; j < 8; ++j) {
        float2 bb = *reinterpret_cast<const float2*>(bias + (8*j + 2*tig) * 4);
        D[4*j+0] = bb.x; D[4*j+1] = bb.y; D[4*j+2] = bb.x; D[4*j+3] = bb.y;
        D[32+4*j+0] = bb.x; D[32+4*j+1] = bb.y;
        D[32+4*j+2] = bb.x; D[32+4*j+3] = bb.y;
    }
#pragma unroll
    for (int j = 0; j < 8; ++j) {
#pragma unroll
        for (int ktp = 0; ktp < 2; ++ktp) {
            uint4 f = *reinterpret_cast<const uint4*>(
                Wf + (((ktp * 8 + j) * 32) + lane) * 16);
            mma8(D + 4*j,      AH[8*ktp+0],  AH[8*ktp+1],  AH[8*ktp+2],
                 AH[8*ktp+3],  f.x, f.y);
            mma8(D + 4*j,      AH[8*ktp+4],  AH[8*ktp+5],  AH[8*ktp+6],
                 AH[8*ktp+7],  f.z, f.w);
            mma8(D + 32 + 4*j, AH[16+8*ktp+0], AH[16+8*ktp+1], AH[16+8*ktp+2],
                 AH[16+8*ktp+3], f.x, f.y);
            mma8(D + 32 + 4*j, AH[16+8*ktp+4], AH[16+8*ktp+5], AH[16+8*ktp+6],
                 AH[16+8*ktp+7], f.z, f.w);
        }
    }
}

__global__ __launch_bounds__(LNN_NT, 2)
void lnn2276_v12_kernel(const float* __restrict__ x,
                        const float* __restrict__ ts,
                        const float* __restrict__ gWin, const float* __restrict__ gbin,
                        const float* __restrict__ gW1,  const float* __restrict__ gb1,
                        const float* __restrict__ gW2,  const float* __restrict__ gb2,
                        const float* __restrict__ gWout, const float* __restrict__ gbout,
                        float* __restrict__ out, int B) {
    extern __shared__ char sm[];
    const int tid  = threadIdx.x;
    const int w    = tid >> 5;
    const int lane = tid & 31;
    const int g    = lane >> 2;
    const int tig  = lane & 3;

    // ---- prologue: W fragments, 2 kt per uint4 ----
    for (int p = tid; p < 512; p += LNN_NT) {
        int ktp = p >> 8, j = (p >> 5) & 7, ln = p & 31;
        int tg = ln & 3, gg = ln >> 2;
        int n  = 8 * j + gg;
        uint32_t v[2][2];
#pragma unroll
        for (int e = 0; e < 2; ++e) {
            int k0 = (2 * ktp + e) * 16 + 2 * tg;
            v[e][0] = packh2(gW1[k0 * 64 + n],       gW1[(k0 + 1) * 64 + n]);
            v[e][1] = packh2(gW1[(k0 + 8) * 64 + n], gW1[(k0 + 9) * 64 + n]);
        }
        *reinterpret_cast<uint4*>(sm + OFF_W1 + p * 16) =
            make_uint4(v[0][0], v[0][1], v[1][0], v[1][1]);
#pragma unroll
        for (int e = 0; e < 2; ++e) {
            int k0 = (2 * ktp + e) * 16 + 2 * tg;
            v[e][0] = packh2(gW2[k0 * 64 + n],       gW2[(k0 + 1) * 64 + n]);
            v[e][1] = packh2(gW2[(k0 + 8) * 64 + n], gW2[(k0 + 9) * 64 + n]);
        }
        *reinterpret_cast<uint4*>(sm + OFF_W2 + p * 16) =
            make_uint4(v[0][0], v[0][1], v[1][0], v[1][1]);
    }
    if (tid < 64) {
        *(float*)(sm + OFF_B1 + tid * 4) = gb1[tid];
        *(float*)(sm + OFF_B2 + tid * 4) = gb2[tid];
    }
    __syncthreads();

    const float dt = (ts[1] - ts[0]) * (1.0f / (float)LNN_NSTEPS);
    const int rowbase = blockIdx.x * LNN_M + w * 32 + g;

    // ---- y0 = x @ Win + bin (blk-major D-fragment layout, 64 values) ----
    float y[64];
#pragma unroll
    for (int blk = 0; blk < 2; ++blk) {
        const int r1 = rowbase + blk * 16;
        const int r2 = r1 + 8;
        float xr1[LNN_DIN], xr2[LNN_DIN];
#pragma unroll
        for (int k = 0; k < LNN_DIN; ++k) {
            xr1[k] = (r1 < B) ? __ldg(&x[(size_t)r1 * LNN_DIN + k]) : 0.0f;
            xr2[k] = (r2 < B) ? __ldg(&x[(size_t)r2 * LNN_DIN + k]) : 0.0f;
        }
#pragma unroll
        for (int j = 0; j < 8; ++j) {
            int c0 = 8 * j + 2 * tig;
            float s0 = __ldg(&gbin[c0]);
            float s1 = __ldg(&gbin[c0 + 1]);
            float a0 = s0, a1 = s1, a2 = s0, a3 = s1;
#pragma unroll
            for (int k = 0; k < LNN_DIN; ++k) {
                float w0 = __ldg(&gWin[k * 64 + c0]);
                float w1 = __ldg(&gWin[k * 64 + c0 + 1]);
                a0 = fmaf(xr1[k], w0, a0);
                a1 = fmaf(xr1[k], w1, a1);
                a2 = fmaf(xr2[k], w0, a2);
                a3 = fmaf(xr2[k], w1, a3);
            }
            y[blk*32 + 4*j + 0] = a0; y[blk*32 + 4*j + 1] = a1;
            y[blk*32 + 4*j + 2] = a2; y[blk*32 + 4*j + 3] = a3;
        }
    }

    // thread-private k slice: + m*16384 + blk*2048 + p*512
    char* kT = sm + OFF_K + (size_t)w * 4096 + (size_t)lane * 16;

    uint32_t AH[32];
    float D[64];

#pragma unroll 1
    for (int step = 0; step < LNN_NSTEPS; ++step) {
#pragma unroll 1
        for (int s = 0; s < 6; ++s) {
            if (s == 0) {
                // stage 1: v = y
#pragma unroll
                for (int i = 0; i < 32; ++i)
                    AH[i] = packh2(y[2*i], y[2*i + 1]);
            } else {
                // D holds k_s. Pack it once: store (s<=4) + gamma-term into AH.
                float gf = dt * GAM[s];
                uint32_t g2 = packh2(gf, gf);
                char* ab = kT + (s - 1) * 16384;
#pragma unroll
                for (int blk = 0; blk < 2; ++blk)
#pragma unroll
                    for (int p = 0; p < 4; ++p) {
                        int yb = blk * 32 + 8 * p;
                        int hb = blk * 16 + 4 * p;
                        uint4 dh;
                        dh.x = packh2(D[yb+0], D[yb+1]);
                        dh.y = packh2(D[yb+2], D[yb+3]);
                        dh.z = packh2(D[yb+4], D[yb+5]);
                        dh.w = packh2(D[yb+6], D[yb+7]);
                        if (s <= 4)
                            *reinterpret_cast<uint4*>(ab + blk * 2048 + p * 512) = dh;
                        AH[hb+0] = hfma2u(g2, dh.x, packh2(y[yb+0], y[yb+1]));
                        AH[hb+1] = hfma2u(g2, dh.y, packh2(y[yb+2], y[yb+3]));
                        AH[hb+2] = hfma2u(g2, dh.z, packh2(y[yb+4], y[yb+5]));
                        AH[hb+3] = hfma2u(g2, dh.w, packh2(y[yb+6], y[yb+7]));
                    }
                // rebased array terms: k_1..k_{s-1} with coeff dt*(a - b)
#pragma unroll 1
                for (int i = 0; i + 1 < s; ++i) {
                    float cf = dt * ACB[s][i];
                    uint32_t c2 = packh2(cf, cf);
                    const char* ib = kT + i * 16384;
#pragma unroll
                    for (int blk = 0; blk < 2; ++blk)
#pragma unroll
                        for (int p = 0; p < 4; ++p) {
                            uint4 a = *reinterpret_cast<const uint4*>(
                                ib + blk * 2048 + p * 512);
                            int hb = blk * 16 + 4 * p;
                            AH[hb + 0] = hfma2u(c2, a.x, AH[hb + 0]);
                            AH[hb + 1] = hfma2u(c2, a.y, AH[hb + 1]);
                            AH[hb + 2] = hfma2u(c2, a.z, AH[hb + 2]);
                            AH[hb + 3] = hfma2u(c2, a.w, AH[hb + 3]);
                        }
                }
                // fold y += dt*b_s * k_s (fp32, D still = k_s); b2 == 0 skip
                if (s != 2) {
                    float bf = dt * Bb[s - 1];
#pragma unroll
                    for (int i = 0; i < 64; ++i)
                        y[i] = fmaf(bf, D[i], y[i]);
                }
            }
            // ---- GEMM1 (bias-init), tanh ----
            gemm1p(D, AH, sm + OFF_W1, sm + OFF_B1, lane, tig);
#pragma unroll
            for (int blk = 0; blk < 2; ++blk)
#pragma unroll
                for (int j = 0; j < 8; ++j) {
                    int db = blk * 32 + 4 * j;
                    float t0 = tanh_ap(D[db+0]);
                    float t1 = tanh_ap(D[db+1]);
                    float t2 = tanh_ap(D[db+2]);
                    float t3 = tanh_ap(D[db+3]);
                    int t4 = blk * 16 + 4 * (j >> 1) + 2 * (j & 1);
                    AH[t4]     = packh2(t0, t1);
                    AH[t4 + 1] = packh2(t2, t3);
                }
            // ---- GEMM2 (bias-init) -> D = k_{s+1} ----
            gemm1p(D, AH, sm + OFF_W2, sm + OFF_B2, lane, tig);
        }
        // ---- end of step: D = k6; y += dt*b6*k6 (fp32) ----
        {
            float bf = dt * Bb[5];
#pragma unroll
            for (int i = 0; i < 64; ++i)
                y[i] = fmaf(bf, D[i], y[i]);
        }
    }

    // ---- out = y @ Wout + bout (quad shfl reduction, per block) ----
#pragma unroll
    for (int blk = 0; blk < 2; ++blk) {
        float o1[LNN_DOUT] = {0.f, 0.f, 0.f};
        float o2[LNN_DOUT] = {0.f, 0.f, 0.f};
#pragma unroll
        for (int j = 0; j < 8; ++j) {
#pragma unroll
            for (int e = 0; e < 2; ++e) {
                int col = 8 * j + 2 * tig + e;
#pragma unroll
                for (int q = 0; q < LNN_DOUT; ++q) {
                    float wv = __ldg(&gWout[col * LNN_DOUT + q]);
                    o1[q] = fmaf(y[blk*32 + 4*j + e],     wv, o1[q]);
                    o2[q] = fmaf(y[blk*32 + 4*j + 2 + e], wv, o2[q]);
                }
            }
        }
#pragma unroll
        for (int q = 0; q < LNN_DOUT; ++q) {
            o1[q] += __shfl_xor_sync(0xffffffffu, o1[q], 1);
            o1[q] += __shfl_xor_sync(0xffffffffu, o1[q], 2);
            o2[q] += __shfl_xor_sync(0xffffffffu, o2[q], 1);
            o2[q] += __shfl_xor_sync(0xffffffffu, o2[q], 2);
        }
        if (tig == 0) {
            const int r1 = rowbase + blk * 16;
            const int r2 = r1 + 8;
#pragma unroll
            for (int q = 0; q < LNN_DOUT; ++q) {
                float bo = __ldg(&gbout[q]);
                if (r1 < B) out[(size_t)r1 * LNN_DOUT + q] = o1[q] + bo;
                if (r2 < B) out[(size_t)r2 * LNN_DOUT + q] = o2[q] + bo;
            }
        }
    }
}

extern "C" void kernel_launch(void* const* d_in, const int* in_sizes, int n_in,
                              void* d_out, int out_size) {
    const float* x    = (const float*)d_in[0];
    const float* ts   = (const float*)d_in[1];
    const float* Win  = (const float*)d_in[2];
    const float* bin  = (const float*)d_in[3];
    const float* W1   = (const float*)d_in[4];
    const float* b1   = (const float*)d_in[5];
    const float* W2   = (const float*)d_in[6];
    const float* b2   = (const float*)d_in[7];
    const float* Wout = (const float*)d_in[8];
    const float* bout = (const float*)d_in[9];
    float* out = (float*)d_out;

    int B = in_sizes[0] / LNN_DIN;
    cudaFuncSetAttribute(lnn2276_v12_kernel,
                         cudaFuncAttributeMaxDynamicSharedMemorySize, SMEM_SZ);
    int grid = (B + LNN_M - 1) / LNN_M;
    lnn2276_v12_kernel<<<grid, LNN_NT, SMEM_SZ>>>(x, ts, Win, bin, W1, b1, W2, b2,
                                                  Wout, bout, out, B);
}

// round 13
// speedup vs baseline: 2.6318x; 1.0005x over previous
#include <cuda_runtime.h>
#include <cuda_fp16.h>
#include <cstdint>

// ---------------------------------------------------------------------------
// LiquidNeuralNetwork via mma.sync HMMA, M=32 per warp (2x m16 blocks).
// Single-product GEMMs A(fp16)@W(fp16), fp32 accum. Bias enters as the C
// operand of the FIRST MMA of each accumulation chain (no D-init MOVs).
// DOPRI5 incremental-fold: y += dt*b_s*k_s in fp32 per stage (k_s in regs);
// stage inputs rebased v_s = Y_{s-2} + dt*sum (a_si - b_i) k_i + dt*a_{s,s-1}*D.
// Only k1..k4 stored (fp16, 4 arrays); k5/k6 consumed from registers.
// CTA = 128 rows / 4 warps, 2 CTAs/SM.
// ---------------------------------------------------------------------------

#define LNN_DIN    14
#define LNN_DOUT   3
#define LNN_M      128
#define LNN_NT     128
#define LNN_NSTEPS 32

// SMEM byte offsets
#define OFF_W1   0            // [2ktp][8j][32lane] uint4 = 8KB
#define OFF_W2   8192
#define OFF_K    16384        // 4 k-arrays x 16KB: [m][w][blk][p][lane] uint4
#define OFF_B1   81920        // 64 f32
#define OFF_B2   82176
#define SMEM_SZ  82432

// gamma: GAM[s] = a_{s+1,s} (coeff of k_s from D regs in stage s+1 input)
static __device__ constexpr float GAM[6] = {
    0.f, (float)(1.0/5.0), (float)(9.0/40.0), (float)(32.0/9.0),
    (float)(-212.0/729.0), (float)(-5103.0/18656.0)};
// ACB[s][i] = a_{s+1,i+1} - b_{i+1}  (array terms, rebased)
static __device__ constexpr float ACB[6][4] = {
    {0.f, 0.f, 0.f, 0.f},
    {0.f, 0.f, 0.f, 0.f},
    {(float)(3.0/40.0 - 35.0/384.0), 0.f, 0.f, 0.f},
    {(float)(44.0/45.0 - 35.0/384.0), (float)(-56.0/15.0), 0.f, 0.f},
    {(float)(19372.0/6561.0 - 35.0/384.0), (float)(-25360.0/2187.0),
     (float)(64448.0/6561.0 - 500.0/1113.0), 0.f},
    {(float)(9017.0/3168.0 - 35.0/384.0), (float)(-355.0/33.0),
     (float)(46732.0/5247.0 - 500.0/1113.0), (float)(49.0/176.0 - 125.0/192.0)},
};
// Bb[s-1] = b_s (fold coefficient when D = k_s)
static __device__ constexpr float Bb[6] = {
    (float)(35.0/384.0), 0.f, (float)(500.0/1113.0), (float)(125.0/192.0),
    (float)(-2187.0/6784.0), (float)(11.0/84.0)};

__device__ __forceinline__ void mma8(float* d, uint32_t a0, uint32_t a1,
                                     uint32_t a2, uint32_t a3,
                                     uint32_t b0, uint32_t b1) {
    asm("mma.sync.aligned.m16n8k16.row.col.f32.f16.f16.f32 "
        "{%0,%1,%2,%3}, {%4,%5,%6,%7}, {%8,%9}, {%0,%1,%2,%3};"
        : "+f"(d[0]), "+f"(d[1]), "+f"(d[2]), "+f"(d[3])
        : "r"(a0), "r"(a1), "r"(a2), "r"(a3), "r"(b0), "r"(b1));
}
// First MMA of a chain: D = A*B + (cx, cy, cx, cy)  (bias as C operand)
__device__ __forceinline__ void mma8c(float* d, uint32_t a0, uint32_t a1,
                                      uint32_t a2, uint32_t a3,
                                      uint32_t b0, uint32_t b1,
                                      float cx, float cy) {
    asm("mma.sync.aligned.m16n8k16.row.col.f32.f16.f16.f32 "
        "{%0,%1,%2,%3}, {%4,%5,%6,%7}, {%8,%9}, {%10,%11,%10,%11};"
        : "=f"(d[0]), "=f"(d[1]), "=f"(d[2]), "=f"(d[3])
        : "r"(a0), "r"(a1), "r"(a2), "r"(a3), "r"(b0), "r"(b1),
          "f"(cx), "f"(cy));
}

__device__ __forceinline__ uint32_t packh2(float a, float b) {
    __half2 h = __floats2half2_rn(a, b);
    return *reinterpret_cast<uint32_t*>(&h);
}
__device__ __forceinline__ uint32_t hfma2u(uint32_t a, uint32_t b, uint32_t c) {
    __half2 r = __hfma2(*reinterpret_cast<__half2*>(&a),
                        *reinterpret_cast<__half2*>(&b),
                        *reinterpret_cast<__half2*>(&c));
    return *reinterpret_cast<uint32_t*>(&r);
}
__device__ __forceinline__ float tanh_ap(float x) {
    float r;
    asm("tanh.approx.f32 %0, %1;" : "=f"(r) : "f"(x));
    return r;
}

// D{0,1} = bias + A{0,1}(fp16) @ W(fp16). Bias via C operand of first MMA.
__device__ __forceinline__ void gemm1p(float* D, const uint32_t* AH,
                                       const char* Wf, const char* bias,
                                       int lane, int tig) {
#pragma unroll
    for (int j = 0; j < 8; ++j) {
        float2 bb = *reinterpret_cast<const float2*>(bias + (8*j + 2*tig) * 4);
        uint4 f0 = *reinterpret_cast<const uint4*>(
            Wf + ((j * 32) + lane) * 16);
        uint4 f1 = *reinterpret_cast<const uint4*>(
            Wf + (((8 + j) * 32) + lane) * 16);
        // block 0 chain
        mma8c(D + 4*j, AH[0],  AH[1],  AH[2],  AH[3],  f0.x, f0.y, bb.x, bb.y);
        mma8 (D + 4*j, AH[4],  AH[5],  AH[6],  AH[7],  f0.z, f0.w);
        mma8 (D + 4*j, AH[8],  AH[9],  AH[10], AH[11], f1.x, f1.y);
        mma8 (D + 4*j, AH[12], AH[13], AH[14], AH[15], f1.z, f1.w);
        // block 1 chain
        mma8c(D + 32 + 4*j, AH[16], AH[17], AH[18], AH[19], f0.x, f0.y,
              bb.x, bb.y);
        mma8 (D + 32 + 4*j, AH[20], AH[21], AH[22], AH[23], f0.z, f0.w);
        mma8 (D + 32 + 4*j, AH[24], AH[25], AH[26], AH[27], f1.x, f1.y);
        mma8 (D + 32 + 4*j, AH[28], AH[29], AH[30], AH[31], f1.z, f1.w);
    }
}

__global__ __launch_bounds__(LNN_NT, 2)
void lnn2276_v13_kernel(const float* __restrict__ x,
                        const float* __restrict__ ts,
                        const float* __restrict__ gWin, const float* __restrict__ gbin,
                        const float* __restrict__ gW1,  const float* __restrict__ gb1,
                        const float* __restrict__ gW2,  const float* __restrict__ gb2,
                        const float* __restrict__ gWout, const float* __restrict__ gbout,
                        float* __restrict__ out, int B) {
    extern __shared__ char sm[];
    const int tid  = threadIdx.x;
    const int w    = tid >> 5;
    const int lane = tid & 31;
    const int g    = lane >> 2;
    const int tig  = lane & 3;

    // ---- prologue: W fragments, 2 kt per uint4 ----
    for (int p = tid; p < 512; p += LNN_NT) {
        int ktp = p >> 8, j = (p >> 5) & 7, ln = p & 31;
        int tg = ln & 3, gg = ln >> 2;
        int n  = 8 * j + gg;
        uint32_t v[2][2];
#pragma unroll
        for (int e = 0; e < 2; ++e) {
            int k0 = (2 * ktp + e) * 16 + 2 * tg;
            v[e][0] = packh2(gW1[k0 * 64 + n],       gW1[(k0 + 1) * 64 + n]);
            v[e][1] = packh2(gW1[(k0 + 8) * 64 + n], gW1[(k0 + 9) * 64 + n]);
        }
        *reinterpret_cast<uint4*>(sm + OFF_W1 + p * 16) =
            make_uint4(v[0][0], v[0][1], v[1][0], v[1][1]);
#pragma unroll
        for (int e = 0; e < 2; ++e) {
            int k0 = (2 * ktp + e) * 16 + 2 * tg;
            v[e][0] = packh2(gW2[k0 * 64 + n],       gW2[(k0 + 1) * 64 + n]);
            v[e][1] = packh2(gW2[(k0 + 8) * 64 + n], gW2[(k0 + 9) * 64 + n]);
        }
        *reinterpret_cast<uint4*>(sm + OFF_W2 + p * 16) =
            make_uint4(v[0][0], v[0][1], v[1][0], v[1][1]);
    }
    if (tid < 64) {
        *(float*)(sm + OFF_B1 + tid * 4) = gb1[tid];
        *(float*)(sm + OFF_B2 + tid * 4) = gb2[tid];
    }
    __syncthreads();

    const float dt = (ts[1] - ts[0]) * (1.0f / (float)LNN_NSTEPS);
    const int rowbase = blockIdx.x * LNN_M + w * 32 + g;

    // ---- y0 = x @ Win + bin (blk-major D-fragment layout, 64 values) ----
    float y[64];
#pragma unroll
    for (int blk = 0; blk < 2; ++blk) {
        const int r1 = rowbase + blk * 16;
        const int r2 = r1 + 8;
        float xr1[LNN_DIN], xr2[LNN_DIN];
#pragma unroll
        for (int k = 0; k < LNN_DIN; ++k) {
            xr1[k] = (r1 < B) ? __ldg(&x[(size_t)r1 * LNN_DIN + k]) : 0.0f;
            xr2[k] = (r2 < B) ? __ldg(&x[(size_t)r2 * LNN_DIN + k]) : 0.0f;
        }
#pragma unroll
        for (int j = 0; j < 8; ++j) {
            int c0 = 8 * j + 2 * tig;
            float s0 = __ldg(&gbin[c0]);
            float s1 = __ldg(&gbin[c0 + 1]);
            float a0 = s0, a1 = s1, a2 = s0, a3 = s1;
#pragma unroll
            for (int k = 0; k < LNN_DIN; ++k) {
                float w0 = __ldg(&gWin[k * 64 + c0]);
                float w1 = __ldg(&gWin[k * 64 + c0 + 1]);
                a0 = fmaf(xr1[k], w0, a0);
                a1 = fmaf(xr1[k], w1, a1);
                a2 = fmaf(xr2[k], w0, a2);
                a3 = fmaf(xr2[k], w1, a3);
            }
            y[blk*32 + 4*j + 0] = a0; y[blk*32 + 4*j + 1] = a1;
            y[blk*32 + 4*j + 2] = a2; y[blk*32 + 4*j + 3] = a3;
        }
    }

    // thread-private k slice: + m*16384 + blk*2048 + p*512
    char* kT = sm + OFF_K + (size_t)w * 4096 + (size_t)lane * 16;

    uint32_t AH[32];
    float D[64];

#pragma unroll 1
    for (int step = 0; step < LNN_NSTEPS; ++step) {
#pragma unroll 1
        for (int s = 0; s < 6; ++s) {
            if (s == 0) {
                // stage 1: v = y
#pragma unroll
                for (int i = 0; i < 32; ++i)
                    AH[i] = packh2(y[2*i], y[2*i + 1]);
            } else {
                // D holds k_s. Pack it once: store (s<=4) + gamma-term into AH.
                float gf = dt * GAM[s];
                uint32_t g2 = packh2(gf, gf);
                char* ab = kT + (s - 1) * 16384;
#pragma unroll
                for (int blk = 0; blk < 2; ++blk)
#pragma unroll
                    for (int p = 0; p < 4; ++p) {
                        int yb = blk * 32 + 8 * p;
                        int hb = blk * 16 + 4 * p;
                        uint4 dh;
                        dh.x = packh2(D[yb+0], D[yb+1]);
                        dh.y = packh2(D[yb+2], D[yb+3]);
                        dh.z = packh2(D[yb+4], D[yb+5]);
                        dh.w = packh2(D[yb+6], D[yb+7]);
                        if (s <= 4)
                            *reinterpret_cast<uint4*>(ab + blk * 2048 + p * 512) = dh;
                        AH[hb+0] = hfma2u(g2, dh.x, packh2(y[yb+0], y[yb+1]));
                        AH[hb+1] = hfma2u(g2, dh.y, packh2(y[yb+2], y[yb+3]));
                        AH[hb+2] = hfma2u(g2, dh.z, packh2(y[yb+4], y[yb+5]));
                        AH[hb+3] = hfma2u(g2, dh.w, packh2(y[yb+6], y[yb+7]));
                    }
                // rebased array terms: k_1..k_{s-1} with coeff dt*(a - b)
#pragma unroll 1
                for (int i = 0; i + 1 < s; ++i) {
                    float cf = dt * ACB[s][i];
                    uint32_t c2 = packh2(cf, cf);
                    const char* ib = kT + i * 16384;
#pragma unroll
                    for (int blk = 0; blk < 2; ++blk)
#pragma unroll
                        for (int p = 0; p < 4; ++p) {
                            uint4 a = *reinterpret_cast<const uint4*>(
                                ib + blk * 2048 + p * 512);
                            int hb = blk * 16 + 4 * p;
                            AH[hb + 0] = hfma2u(c2, a.x, AH[hb + 0]);
                            AH[hb + 1] = hfma2u(c2, a.y, AH[hb + 1]);
                            AH[hb + 2] = hfma2u(c2, a.z, AH[hb + 2]);
                            AH[hb + 3] = hfma2u(c2, a.w, AH[hb + 3]);
                        }
                }
                // fold y += dt*b_s * k_s (fp32, D still = k_s); b2 == 0 skip
                if (s != 2) {
                    float bf = dt * Bb[s - 1];
#pragma unroll
                    for (int i = 0; i < 64; ++i)
                        y[i] = fmaf(bf, D[i], y[i]);
                }
            }
            // ---- GEMM1 (bias via C operand), tanh ----
            gemm1p(D, AH, sm + OFF_W1, sm + OFF_B1, lane, tig);
#pragma unroll
            for (int blk = 0; blk < 2; ++blk)
#pragma unroll
                for (int j = 0; j < 8; ++j) {
                    int db = blk * 32 + 4 * j;
                    float t0 = tanh_ap(D[db+0]);
                    float t1 = tanh_ap(D[db+1]);
                    float t2 = tanh_ap(D[db+2]);
                    float t3 = tanh_ap(D[db+3]);
                    int t4 = blk * 16 + 4 * (j >> 1) + 2 * (j & 1);
                    AH[t4]     = packh2(t0, t1);
                    AH[t4 + 1] = packh2(t2, t3);
                }
            // ---- GEMM2 (bias via C operand) -> D = k_{s+1} ----
            gemm1p(D, AH, sm + OFF_W2, sm + OFF_B2, lane, tig);
        }
        // ---- end of step: D = k6; y += dt*b6*k6 (fp32) ----
        {
            float bf = dt * Bb[5];
#pragma unroll
            for (int i = 0; i < 64; ++i)
                y[i] = fmaf(bf, D[i], y[i]);
        }
    }

    // ---- out = y @ Wout + bout (quad shfl reduction, per block) ----
#pragma unroll
    for (int blk = 0; blk < 2; ++blk) {
        float o1[LNN_DOUT] = {0.f, 0.f, 0.f};
        float o2[LNN_DOUT] = {0.f, 0.f, 0.f};
#pragma unroll
        for (int j = 0; j < 8; ++j) {
#pragma unroll
            for (int e = 0; e < 2; ++e) {
                int col = 8 * j + 2 * tig + e;
#pragma unroll
                for (int q = 0; q < LNN_DOUT; ++q) {
                    float wv = __ldg(&gWout[col * LNN_DOUT + q]);
                    o1[q] = fmaf(y[blk*32 + 4*j + e],     wv, o1[q]);
                    o2[q] = fmaf(y[blk*32 + 4*j + 2 + e], wv, o2[q]);
                }
            }
        }
#pragma unroll
        for (int q = 0; q < LNN_DOUT; ++q) {
            o1[q] += __shfl_xor_sync(0xffffffffu, o1[q], 1);
            o1[q] += __shfl_xor_sync(0xffffffffu, o1[q], 2);
            o2[q] += __shfl_xor_sync(0xffffffffu, o2[q], 1);
            o2[q] += __shfl_xor_sync(0xffffffffu, o2[q], 2);
        }
        if (tig == 0) {
            const int r1 = rowbase + blk * 16;
            const int r2 = r1 + 8;
#pragma unroll
            for (int q = 0; q < LNN_DOUT; ++q) {
                float bo = __ldg(&gbout[q]);
                if (r1 < B) out[(size_t)r1 * LNN_DOUT + q] = o1[q] + bo;
                if (r2 < B) out[(size_t)r2 * LNN_DOUT + q] = o2[q] + bo;
            }
        }
    }
}

extern "C" void kernel_launch(void* const* d_in, const int* in_sizes, int n_in,
                              void* d_out, int out_size) {
    const float* x    = (const float*)d_in[0];
    const float* ts   = (const float*)d_in[1];
    const float* Win  = (const float*)d_in[2];
    const float* bin  = (const float*)d_in[3];
    const float* W1   = (const float*)d_in[4];
    const float* b1   = (const float*)d_in[5];
    const float* W2   = (const float*)d_in[6];
    const float* b2   = (const float*)d_in[7];
    const float* Wout = (const float*)d_in[8];
    const float* bout = (const float*)d_in[9];
    float* out = (float*)d_out;

    int B = in_sizes[0] / LNN_DIN;
    cudaFuncSetAttribute(lnn2276_v13_kernel,
                         cudaFuncAttributeMaxDynamicSharedMemorySize, SMEM_SZ);
    int grid = (B + LNN_M - 1) / LNN_M;
    lnn2276_v13_kernel<<<grid, LNN_NT, SMEM_SZ>>>(x, ts, Win, bin, W1, b1, W2, b2,
                                                  Wout, bout, out, B);
}